// round 12
// baseline (speedup 1.0000x reference)
#include <cuda_runtime.h>
#include <cuda_fp16.h>
#include <math.h>

// ---------------------------------------------------------------------------
// NNConvNet fused GNN — R11: instruction diet on the R9 structure.
//  * h2 GEMM single-split (h1 fp16 x W2 fp16): h2 is rounded to fp16 for the
//    W3 GEMM anyway, so split precision there was wasted. 48->16 mma/tile.
//  * chunk loop processes h in pairs; x loaded once per pair via LDS.64.
//  * xs stride 36 floats -> aligned STS.128 stores, conflict-free LDS.64.
//  16 warps/CTA, B double-buffered, scalar FFMA/FMNMX epi, red.v2 scatter.
// ---------------------------------------------------------------------------

#define NMAX 20000
#define EMAX 320000
#define BATCH 64
#define NWARPS 16
#define NTHREADS (NWARPS * 32)

typedef unsigned int u32;
typedef unsigned short u16;

__device__ float g_x[NMAX * 32];
__device__ float g_agg[NMAX * 32];
__device__ float g_pooled[BATCH * 32];
__device__ float g_counts[BATCH];

__constant__ int c_IDX[36] = {
    0, 1, 2,  3,  4,  5,
    1, 6, 7,  8,  9,  10,
    2, 7, 11, 12, 13, 14,
    3, 8, 12, 15, 16, 17,
    4, 9, 13, 16, 18, 19,
    5, 10,14, 17, 19, 20};

// ---------------- smem layout ----------------
// floats:
#define F_W1 0        // 160
#define F_B1 160      // 32
#define F_B2 192      // 32
#define F_B3S 224     // 1024 (ends 1248 floats = 4992 B)
// bytes:
#define OFF_W2H 4992                  // 32 rows * 80 B = 2560 (ends 7552)
#define OFF_DSTS 7552                 // 16 warps * 32 int = 2048 (ends 9600)
#define OFF_XS 9600                   // 16*32*36*4 = 73728 (ends 83328)
#define OFF_A 83328                   // 16*32*144 = 73728 (ends 157056)
#define OFF_B 157056                  // 32*2064 = 66048 (ends 223104)
#define A_STRIDE 144
#define B_STRIDE 2064
#define W2_STRIDE 80
#define XS_STRIDE 36
#define SMEM_TOTAL 223104

// ---------------- PTX helpers ----------------
__device__ __forceinline__ u32 smem_u32(const void* p) {
    u32 a;
    asm("{ .reg .u64 t; cvta.to.shared.u64 t, %1; cvt.u32.u64 %0, t; }"
        : "=r"(a) : "l"(p));
    return a;
}
__device__ __forceinline__ void ldsm_x4(u32* r, u32 addr) {
    asm volatile(
        "ldmatrix.sync.aligned.m8n8.x4.shared.b16 {%0,%1,%2,%3}, [%4];"
        : "=r"(r[0]), "=r"(r[1]), "=r"(r[2]), "=r"(r[3]) : "r"(addr));
}
__device__ __forceinline__ void ldsm_x4t(u32* r, u32 addr) {
    asm volatile(
        "ldmatrix.sync.aligned.m8n8.x4.trans.shared.b16 {%0,%1,%2,%3}, [%4];"
        : "=r"(r[0]), "=r"(r[1]), "=r"(r[2]), "=r"(r[3]) : "r"(addr));
}
__device__ __forceinline__ void mma_f16(float* d, const u32* a, u32 b0,
                                        u32 b1) {
    asm volatile(
        "mma.sync.aligned.m16n8k16.row.col.f32.f16.f16.f32 "
        "{%0,%1,%2,%3}, {%4,%5,%6,%7}, {%8,%9}, {%0,%1,%2,%3};"
        : "+f"(d[0]), "+f"(d[1]), "+f"(d[2]), "+f"(d[3])
        : "r"(a[0]), "r"(a[1]), "r"(a[2]), "r"(a[3]), "r"(b0), "r"(b1));
}
__device__ __forceinline__ void red_v2(float* ap, float m0, float m1) {
    asm volatile("red.global.add.v2.f32 [%0], {%1, %2};"
                 :: "l"(ap), "f"(m0), "f"(m1) : "memory");
}

// ---------------------------------------------------------------------------
__global__ void init_kernel(const float* __restrict__ node_attrs,
                            const float* __restrict__ embW,
                            const float* __restrict__ embB, int N) {
    int idx = blockIdx.x * blockDim.x + threadIdx.x;
    if (idx < N * 32) {
        int k = idx & 31;
        g_x[idx] = fmaf(node_attrs[idx >> 5], embW[k], embB[k]);
        g_agg[idx] = 0.f;
    }
    if (idx < BATCH * 32) g_pooled[idx] = 0.f;
    if (idx < BATCH) g_counts[idx] = 0.f;
}

// ---------------------------------------------------------------------------
__global__ void __launch_bounds__(NTHREADS, 1)
edge_kernel(const float* __restrict__ positions,
            const float* __restrict__ shifts,
            const float* __restrict__ edge_attr,
            const int* __restrict__ eidx,
            const float* __restrict__ W1, const float* __restrict__ b1,
            const float* __restrict__ W2, const float* __restrict__ b2,
            const float* __restrict__ W3, const float* __restrict__ b3,
            int E) {
    extern __shared__ float smf[];
    char* smc = (char*)smf;
    const u32 sb = smem_u32(smf);
    const int tid = threadIdx.x;
    const int lane = tid & 31;
    const int warp = tid >> 5;

    // ---- stage B = fp16(W3) in [j][n] layout ----
    for (int i = tid; i < 32768; i += NTHREADS) {
        int j = i >> 10, col = i & 1023;
        __half h = __float2half_rn(W3[i]);
        *(u16*)(smc + OFF_B + j * B_STRIDE + col * 2) = *(u16*)&h;
    }
    // ---- W2 fp16 (single precision level) [j][n] ----
    for (int i = tid; i < 1024; i += NTHREADS) {
        int j = i >> 5, n = i & 31;
        __half hh = __float2half_rn(W2[i]);
        *(u16*)(smc + OFF_W2H + j * W2_STRIDE + n * 2) = *(u16*)&hh;
        smf[F_B3S + i] = b3[i];
    }
    if (tid < 160) smf[F_W1 + tid] = W1[tid];
    if (tid < 32) {
        smf[F_B1 + tid] = b1[tid];
        smf[F_B2 + tid] = b2[tid];
    }
    __syncthreads();

    const int g = lane >> 2;     // fragment row group
    const int tq = lane & 3;     // fragment col group
    char* arow_base = smc + OFF_A + (warp * 32) * A_STRIDE;
    const u32 aw = sb + OFF_A + (u32)(warp * 32) * A_STRIDE;
    float* xw = smf + (OFF_XS / 4) + warp * (32 * XS_STRIDE);
    int* dstw = (int*)(smc + OFF_DSTS) + warp * 32;

    const int rowoff = ((lane >> 3) & 1) * 8 + (lane & 7);
    const int colb16 = (lane >> 4) * 16;

    const int* srcp = eidx;
    const int* dstp = eidx + E;
    const int ntiles = (E + 31) >> 5;
    const int gw = blockIdx.x * NWARPS + warp;
    const int gstride = gridDim.x * NWARPS;

#define LOADB(FR, C)                                                        \
    do {                                                                    \
        u32 _bc = sb + OFF_B + (u32)((C) * 64 + colb16);                    \
        ldsm_x4t(FR[0], _bc + (u32)(rowoff * B_STRIDE));                    \
        ldsm_x4t(FR[1], _bc + (u32)((rowoff + 16) * B_STRIDE));             \
        ldsm_x4t(FR[2], _bc + 32 + (u32)(rowoff * B_STRIDE));               \
        ldsm_x4t(FR[3], _bc + 32 + (u32)((rowoff + 16) * B_STRIDE));        \
    } while (0)

#define CHUNK_BODY(BB, C, X00, X01, X10, X11)                               \
    do {                                                                    \
        const int _cb = (C) * 32;                                           \
        float acc[2][4][4];                                                 \
        _Pragma("unroll") for (int n8 = 0; n8 < 4; n8++) {                  \
            float2 bv =                                                     \
                *(const float2*)(smf + F_B3S + _cb + n8 * 8 + 2 * tq);      \
            _Pragma("unroll") for (int mt = 0; mt < 2; mt++) {              \
                acc[mt][n8][0] = bv.x;                                      \
                acc[mt][n8][1] = bv.y;                                      \
                acc[mt][n8][2] = bv.x;                                      \
                acc[mt][n8][3] = bv.y;                                      \
            }                                                               \
        }                                                                   \
        mma_f16(acc[0][0], Ah[0][0], BB[0][0], BB[0][1]);                   \
        mma_f16(acc[0][1], Ah[0][0], BB[0][2], BB[0][3]);                   \
        mma_f16(acc[1][0], Ah[1][0], BB[0][0], BB[0][1]);                   \
        mma_f16(acc[1][1], Ah[1][0], BB[0][2], BB[0][3]);                   \
        mma_f16(acc[0][2], Ah[0][0], BB[2][0], BB[2][1]);                   \
        mma_f16(acc[0][3], Ah[0][0], BB[2][2], BB[2][3]);                   \
        mma_f16(acc[1][2], Ah[1][0], BB[2][0], BB[2][1]);                   \
        mma_f16(acc[1][3], Ah[1][0], BB[2][2], BB[2][3]);                   \
        mma_f16(acc[0][0], Ah[0][1], BB[1][0], BB[1][1]);                   \
        mma_f16(acc[0][1], Ah[0][1], BB[1][2], BB[1][3]);                   \
        mma_f16(acc[1][0], Ah[1][1], BB[1][0], BB[1][1]);                   \
        mma_f16(acc[1][1], Ah[1][1], BB[1][2], BB[1][3]);                   \
        mma_f16(acc[0][2], Ah[0][1], BB[3][0], BB[3][1]);                   \
        mma_f16(acc[0][3], Ah[0][1], BB[3][2], BB[3][3]);                   \
        mma_f16(acc[1][2], Ah[1][1], BB[3][0], BB[3][1]);                   \
        mma_f16(acc[1][3], Ah[1][1], BB[3][2], BB[3][3]);                   \
        _Pragma("unroll") for (int t = 0; t < 4; t++) {                     \
            const float* d0 = acc[0][t];                                    \
            msg[0][0][2 * t] = fmaf(X00, fmaxf(d0[0], 0.f),                 \
                                    msg[0][0][2 * t]);                      \
            msg[0][0][2 * t + 1] = fmaf(X00, fmaxf(d0[1], 0.f),             \
                                        msg[0][0][2 * t + 1]);              \
            msg[0][1][2 * t] = fmaf(X01, fmaxf(d0[2], 0.f),                 \
                                    msg[0][1][2 * t]);                      \
            msg[0][1][2 * t + 1] = fmaf(X01, fmaxf(d0[3], 0.f),             \
                                        msg[0][1][2 * t + 1]);              \
            const float* d1 = acc[1][t];                                    \
            msg[1][0][2 * t] = fmaf(X10, fmaxf(d1[0], 0.f),                 \
                                    msg[1][0][2 * t]);                      \
            msg[1][0][2 * t + 1] = fmaf(X10, fmaxf(d1[1], 0.f),             \
                                        msg[1][0][2 * t + 1]);              \
            msg[1][1][2 * t] = fmaf(X11, fmaxf(d1[2], 0.f),                 \
                                    msg[1][1][2 * t]);                      \
            msg[1][1][2 * t + 1] = fmaf(X11, fmaxf(d1[3], 0.f),             \
                                        msg[1][1][2 * t + 1]);              \
        }                                                                   \
    } while (0)

    for (int tile = gw; tile < ntiles; tile += gstride) {
        // ================= phase 1: thread = edge, h1 only =================
        int e = (tile << 5) + lane;
        bool valid = e < E;
        float vx = 0.f, vy = 0.f, vz = 0.f, ea = 0.f;
        int si = 0, di = -1;
        if (valid) {
            si = srcp[e];
            di = dstp[e];
            float px = positions[si * 3 + 0], py = positions[si * 3 + 1],
                  pz = positions[si * 3 + 2];
            float qx = positions[di * 3 + 0], qy = positions[di * 3 + 1],
                  qz = positions[di * 3 + 2];
            vx = qx - px + shifts[e * 3 + 0];
            vy = qy - py + shifts[e * 3 + 1];
            vz = qz - pz + shifts[e * 3 + 2];
            ea = edge_attr[e];
        }
        dstw[lane] = valid ? di : -1;
        float len = sqrtf(vx * vx + vy * vy + vz * vz);

        float h1[32];
#pragma unroll
        for (int k = 0; k < 32; k++) {
            float a = smf[F_B1 + k];
            a = fmaf(vx, smf[F_W1 + 0 * 32 + k], a);
            a = fmaf(vy, smf[F_W1 + 1 * 32 + k], a);
            a = fmaf(vz, smf[F_W1 + 2 * 32 + k], a);
            a = fmaf(len, smf[F_W1 + 3 * 32 + k], a);
            a = fmaf(ea, smf[F_W1 + 4 * 32 + k], a);
            h1[k] = fmaxf(a, 0.f);
        }

        // h1 -> fp16 A row (high only; h2 result is fp16 anyway)
        {
            char* arow = arow_base + lane * A_STRIDE;
#pragma unroll
            for (int t = 0; t < 16; t++) {
                __half2 hh = __floats2half2_rn(h1[2 * t], h1[2 * t + 1]);
                *(u32*)(arow + 4 * t) = *(u32*)&hh;
            }
        }
        // x[src] -> xs (stride 36: aligned STS.128)
        if (valid) {
            const float4* xr = (const float4*)(g_x + (size_t)si * 32);
            float* xd = xw + lane * XS_STRIDE;
#pragma unroll
            for (int t = 0; t < 8; t++) *(float4*)(xd + 4 * t) = xr[t];
        }
        __syncwarp();

        // ============ h2 GEMM: h2 = relu(h1 @ W2 + b2), single split ========
        {
            u32 A1h[2][2][4];
#pragma unroll
            for (int mt = 0; mt < 2; mt++)
#pragma unroll
                for (int kk = 0; kk < 2; kk++) {
                    u32 a = aw + (u32)((mt * 16 + rowoff) * A_STRIDE) +
                            (u32)(kk * 32 + colb16);
                    ldsm_x4(A1h[mt][kk], a);
                }

#pragma unroll
            for (int ni = 0; ni < 2; ni++) {
                u32 bch = sb + OFF_W2H + (u32)(ni * 32 + colb16);
                u32 b0h[4], b1h[4];
                ldsm_x4t(b0h, bch + (u32)(rowoff * W2_STRIDE));
                ldsm_x4t(b1h, bch + (u32)((rowoff + 16) * W2_STRIDE));

                float a2[2][2][4];
#pragma unroll
                for (int n8l = 0; n8l < 2; n8l++) {
                    float2 bb = *(const float2*)(smf + F_B2 +
                                                 (ni * 2 + n8l) * 8 + 2 * tq);
#pragma unroll
                    for (int mt = 0; mt < 2; mt++) {
                        a2[mt][n8l][0] = bb.x;
                        a2[mt][n8l][1] = bb.y;
                        a2[mt][n8l][2] = bb.x;
                        a2[mt][n8l][3] = bb.y;
                    }
                }
                mma_f16(a2[0][0], A1h[0][0], b0h[0], b0h[1]);
                mma_f16(a2[0][1], A1h[0][0], b0h[2], b0h[3]);
                mma_f16(a2[1][0], A1h[1][0], b0h[0], b0h[1]);
                mma_f16(a2[1][1], A1h[1][0], b0h[2], b0h[3]);
                mma_f16(a2[0][0], A1h[0][1], b1h[0], b1h[1]);
                mma_f16(a2[0][1], A1h[0][1], b1h[2], b1h[3]);
                mma_f16(a2[1][0], A1h[1][1], b1h[0], b1h[1]);
                mma_f16(a2[1][1], A1h[1][1], b1h[2], b1h[3]);

                // write-out: relu -> fp16
#pragma unroll
                for (int mt = 0; mt < 2; mt++)
#pragma unroll
                    for (int n8l = 0; n8l < 2; n8l++) {
                        int cbyte = ((ni * 2 + n8l) * 8 + 2 * tq) * 2;
                        char* r0p =
                            arow_base + (mt * 16 + g) * A_STRIDE + cbyte;
                        char* r8p = r0p + 8 * A_STRIDE;
                        const float* d = a2[mt][n8l];
                        float f0 = fmaxf(d[0], 0.f), f1 = fmaxf(d[1], 0.f);
                        float f2 = fmaxf(d[2], 0.f), f3 = fmaxf(d[3], 0.f);
                        __half2 h0 = __floats2half2_rn(f0, f1);
                        __half2 h8 = __floats2half2_rn(f2, f3);
                        *(u32*)r0p = *(u32*)&h0;
                        *(u32*)r8p = *(u32*)&h8;
                    }
            }
        }
        __syncwarp();

        // ================= main A fragments (h2 fp16) ========
        u32 Ah[2][2][4];
#pragma unroll
        for (int mt = 0; mt < 2; mt++)
#pragma unroll
            for (int kk = 0; kk < 2; kk++) {
                u32 a = aw + (u32)((mt * 16 + rowoff) * A_STRIDE) +
                        (u32)(kk * 32 + colb16);
                ldsm_x4(Ah[mt][kk], a);
            }

        float msg[2][2][8];
#pragma unroll
        for (int a = 0; a < 2; a++)
#pragma unroll
            for (int hf = 0; hf < 2; hf++)
#pragma unroll
                for (int t = 0; t < 8; t++) msg[a][hf][t] = 0.f;

        // ====== 32 chunks of n=32 (chunk == h), paired h, B prefetched ======
        u32 bbA[4][4], bbB[4][4];
        LOADB(bbA, 0);
#pragma unroll 1
        for (int c = 0; c < 32; c += 2) {
            LOADB(bbB, c + 1);
            float2 xp00 = *(const float2*)(xw + (g) * XS_STRIDE + c);
            float2 xp01 = *(const float2*)(xw + (8 + g) * XS_STRIDE + c);
            float2 xp10 = *(const float2*)(xw + (16 + g) * XS_STRIDE + c);
            float2 xp11 = *(const float2*)(xw + (24 + g) * XS_STRIDE + c);
            CHUNK_BODY(bbA, c, xp00.x, xp01.x, xp10.x, xp11.x);
            if (c + 2 < 32) LOADB(bbA, c + 2);
            CHUNK_BODY(bbB, c + 1, xp00.y, xp01.y, xp10.y, xp11.y);
        }

        // ================= scatter (vector atomics) =================
#pragma unroll
        for (int mt = 0; mt < 2; mt++)
#pragma unroll
            for (int hf = 0; hf < 2; hf++) {
                int row = mt * 16 + hf * 8 + g;
                int d = dstw[row];
                if (d >= 0) {
                    float* ap = g_agg + (size_t)d * 32 + 2 * tq;
#pragma unroll
                    for (int t = 0; t < 4; t++)
                        red_v2(ap + 8 * t, msg[mt][hf][2 * t],
                               msg[mt][hf][2 * t + 1]);
                }
            }
        __syncwarp();
    }
#undef LOADB
#undef CHUNK_BODY
}

// ---------------------------------------------------------------------------
__global__ void node_kernel(const float* __restrict__ conv_b, int N) {
    int idx = blockIdx.x * blockDim.x + threadIdx.x;
    if (idx < N * 32) {
        float v = g_agg[idx] + conv_b[idx & 31];
        g_x[idx] += fmaxf(v, 0.f);
        g_agg[idx] = 0.f;
    }
}

__global__ void pool_kernel(const int* __restrict__ batch_ids, int N) {
    int idx = blockIdx.x * blockDim.x + threadIdx.x;
    if (idx < N * 32) {
        int n = idx >> 5, k = idx & 31;
        int b = batch_ids[n];
        atomicAdd(&g_pooled[b * 32 + k], g_x[idx]);
        if (k == 0) atomicAdd(&g_counts[b], 1.f);
    }
}

__device__ __forceinline__ float selu_f(float x) {
    const float alpha = 1.6732632423543772f;
    const float scale = 1.0507009873554805f;
    return x > 0.f ? scale * x : scale * alpha * expm1f(x);
}

__global__ void mlp_kernel(const float* __restrict__ W1,
                           const float* __restrict__ b1,
                           const float* __restrict__ W2,
                           const float* __restrict__ b2,
                           const float* __restrict__ W3,
                           const float* __restrict__ b3,
                           const float* __restrict__ W4,
                           const float* __restrict__ b4,
                           float* __restrict__ out) {
    __shared__ float sbuf[32][280];
    int warp = threadIdx.x >> 5, lane = threadIdx.x & 31;
    int b = blockIdx.x * 32 + warp;
    if (b >= BATCH) return;
    float* buf = sbuf[warp];

    float cnt = fmaxf(g_counts[b], 1.f);
    buf[lane] = g_pooled[b * 32 + lane] / cnt;
    __syncwarp();

#pragma unroll
    for (int r = 0; r < 4; r++) {
        int o = lane + 32 * r;
        float a = b1[o];
        for (int k = 0; k < 32; k++) a = fmaf(buf[k], W1[k * 128 + o], a);
        buf[32 + o] = selu_f(a);
    }
    __syncwarp();
#pragma unroll
    for (int r = 0; r < 2; r++) {
        int o = lane + 32 * r;
        float a = b2[o];
        for (int k = 0; k < 128; k++) a = fmaf(buf[32 + k], W2[k * 64 + o], a);
        buf[160 + o] = selu_f(a);
    }
    __syncwarp();
    {
        int o = lane;
        float a = b3[o];
        for (int k = 0; k < 64; k++) a = fmaf(buf[160 + k], W3[k * 32 + o], a);
        buf[224 + o] = selu_f(a);
    }
    __syncwarp();
    if (lane < 21) {
        float a = b4[lane];
        for (int k = 0; k < 32; k++) a = fmaf(buf[224 + k], W4[k * 21 + lane], a);
        buf[256 + lane] = a;
    }
    __syncwarp();
    for (int r = lane; r < 36; r += 32) out[b * 36 + r] = buf[256 + c_IDX[r]];
}

// ---------------------------------------------------------------------------
extern "C" void kernel_launch(void* const* d_in, const int* in_sizes, int n_in,
                              void* d_out, int out_size) {
    const float* node_attrs = (const float*)d_in[0];
    const float* positions = (const float*)d_in[1];
    const float* shifts = (const float*)d_in[2];
    const float* edge_attr = (const float*)d_in[3];
    const int* edge_index = (const int*)d_in[4];
    const int* batch_ids = (const int*)d_in[5];
    const float* embed_W = (const float*)d_in[6];
    const float* embed_b = (const float*)d_in[7];
    const float* e_W1 = (const float*)d_in[8];
    const float* e_b1 = (const float*)d_in[9];
    const float* e_W2 = (const float*)d_in[10];
    const float* e_b2 = (const float*)d_in[11];
    const float* e_W3 = (const float*)d_in[12];
    const float* e_b3 = (const float*)d_in[13];
    const float* conv_b = (const float*)d_in[14];
    const float* h_W1 = (const float*)d_in[15];
    const float* h_b1 = (const float*)d_in[16];
    const float* h_W2 = (const float*)d_in[17];
    const float* h_b2 = (const float*)d_in[18];
    const float* h_W3 = (const float*)d_in[19];
    const float* h_b3 = (const float*)d_in[20];
    const float* h_W4 = (const float*)d_in[21];
    const float* h_b4 = (const float*)d_in[22];

    int N = in_sizes[0];
    int E = in_sizes[3];
    if (N > NMAX) N = NMAX;
    if (E > EMAX) E = EMAX;

    cudaFuncSetAttribute(edge_kernel,
                         cudaFuncAttributeMaxDynamicSharedMemorySize,
                         SMEM_TOTAL);

    int tot = N * 32;
    int blk = 256;
    init_kernel<<<(tot + blk - 1) / blk, blk>>>(node_attrs, embed_W, embed_b, N);

    for (int l = 0; l < 3; l++) {
        edge_kernel<<<148, NTHREADS, SMEM_TOTAL>>>(
            positions, shifts, edge_attr, edge_index, e_W1 + l * 160,
            e_b1 + l * 32, e_W2 + l * 1024, e_b2 + l * 32, e_W3 + l * 32768,
            e_b3 + l * 1024, E);
        node_kernel<<<(tot + blk - 1) / blk, blk>>>(conv_b + l * 32, N);
    }

    pool_kernel<<<(tot + blk - 1) / blk, blk>>>(batch_ids, N);
    mlp_kernel<<<2, 1024>>>(h_W1, h_b1, h_W2, h_b2, h_W3, h_b3, h_W4, h_b4,
                            (float*)d_out);
}

// round 13
// speedup vs baseline: 1.1280x; 1.1280x over previous
#include <cuda_runtime.h>
#include <cuda_fp16.h>
#include <math.h>

// ---------------------------------------------------------------------------
// NNConvNet fused GNN — R12: full-fragment MLP (no intermediate smem).
//  h1 = relu(ef_pad @ W1_pad + b1) via mma.m16n8k8 (ef: 1 STS.128 + ldsm.x2;
//       W1 B-frags via ldsm.x4t, 80B stride).
//  h1 D-frags -> relu/cvt -> A-frags of h2 mma (m16n8k16, W2 frags in regs).
//  h2 D-frags -> relu/cvt -> Ah frags of the W3 chunk loop directly.
//  Chunk loop / scatter / B staging unchanged from R11 (measured optimum).
//  16 warps/CTA, B double-buffered, scalar epi, red.v2 scatter.
// ---------------------------------------------------------------------------

#define NMAX 20000
#define EMAX 320000
#define BATCH 64
#define NWARPS 16
#define NTHREADS (NWARPS * 32)

typedef unsigned int u32;
typedef unsigned short u16;

__device__ float g_x[NMAX * 32];
__device__ float g_agg[NMAX * 32];
__device__ float g_pooled[BATCH * 32];
__device__ float g_counts[BATCH];

__constant__ int c_IDX[36] = {
    0, 1, 2,  3,  4,  5,
    1, 6, 7,  8,  9,  10,
    2, 7, 11, 12, 13, 14,
    3, 8, 12, 15, 16, 17,
    4, 9, 13, 16, 18, 19,
    5, 10,14, 17, 19, 20};

// ---------------- smem layout ----------------
// floats:
#define F_B1 0        // 32
#define F_B2 32       // 32
#define F_B3S 64      // 1024 (ends float idx 1088 = 4352 B)
// bytes:
#define OFF_W1H 4352                  // 8 rows * 80 B = 640 (ends 4992)
#define OFF_W2H 4992                  // 32 rows * 80 B = 2560 (ends 7552)
#define OFF_DSTS 7552                 // 16*32*4 = 2048 (ends 9600)
#define OFF_XS 9600                   // 16*32*36*4 = 73728 (ends 83328)
#define OFF_EFS 83328                 // 16*512 = 8192 (ends 91520)
#define OFF_B 91520                   // 32*2064 = 66048 (ends 157568)
#define B_STRIDE 2064
#define W_STRIDE 80
#define XS_STRIDE 36
#define SMEM_TOTAL 157568

// ---------------- PTX helpers ----------------
__device__ __forceinline__ u32 smem_u32(const void* p) {
    u32 a;
    asm("{ .reg .u64 t; cvta.to.shared.u64 t, %1; cvt.u32.u64 %0, t; }"
        : "=r"(a) : "l"(p));
    return a;
}
__device__ __forceinline__ void ldsm_x2(u32* r, u32 addr) {
    asm volatile(
        "ldmatrix.sync.aligned.m8n8.x2.shared.b16 {%0,%1}, [%2];"
        : "=r"(r[0]), "=r"(r[1]) : "r"(addr));
}
__device__ __forceinline__ void ldsm_x4t(u32* r, u32 addr) {
    asm volatile(
        "ldmatrix.sync.aligned.m8n8.x4.trans.shared.b16 {%0,%1,%2,%3}, [%4];"
        : "=r"(r[0]), "=r"(r[1]), "=r"(r[2]), "=r"(r[3]) : "r"(addr));
}
__device__ __forceinline__ void mma_f16(float* d, const u32* a, u32 b0,
                                        u32 b1) {
    asm volatile(
        "mma.sync.aligned.m16n8k16.row.col.f32.f16.f16.f32 "
        "{%0,%1,%2,%3}, {%4,%5,%6,%7}, {%8,%9}, {%0,%1,%2,%3};"
        : "+f"(d[0]), "+f"(d[1]), "+f"(d[2]), "+f"(d[3])
        : "r"(a[0]), "r"(a[1]), "r"(a[2]), "r"(a[3]), "r"(b0), "r"(b1));
}
__device__ __forceinline__ void mma_f16_k8(float* d, const u32* a, u32 b0) {
    asm volatile(
        "mma.sync.aligned.m16n8k8.row.col.f32.f16.f16.f32 "
        "{%0,%1,%2,%3}, {%4,%5}, {%6}, {%0,%1,%2,%3};"
        : "+f"(d[0]), "+f"(d[1]), "+f"(d[2]), "+f"(d[3])
        : "r"(a[0]), "r"(a[1]), "r"(b0));
}
__device__ __forceinline__ void red_v2(float* ap, float m0, float m1) {
    asm volatile("red.global.add.v2.f32 [%0], {%1, %2};"
                 :: "l"(ap), "f"(m0), "f"(m1) : "memory");
}
__device__ __forceinline__ u32 h2u(float lo, float hi) {
    __half2 h = __floats2half2_rn(lo, hi);
    return *(u32*)&h;
}

// ---------------------------------------------------------------------------
__global__ void init_kernel(const float* __restrict__ node_attrs,
                            const float* __restrict__ embW,
                            const float* __restrict__ embB, int N) {
    int idx = blockIdx.x * blockDim.x + threadIdx.x;
    if (idx < N * 32) {
        int k = idx & 31;
        g_x[idx] = fmaf(node_attrs[idx >> 5], embW[k], embB[k]);
        g_agg[idx] = 0.f;
    }
    if (idx < BATCH * 32) g_pooled[idx] = 0.f;
    if (idx < BATCH) g_counts[idx] = 0.f;
}

// ---------------------------------------------------------------------------
__global__ void __launch_bounds__(NTHREADS, 1)
edge_kernel(const float* __restrict__ positions,
            const float* __restrict__ shifts,
            const float* __restrict__ edge_attr,
            const int* __restrict__ eidx,
            const float* __restrict__ W1, const float* __restrict__ b1,
            const float* __restrict__ W2, const float* __restrict__ b2,
            const float* __restrict__ W3, const float* __restrict__ b3,
            int E) {
    extern __shared__ float smf[];
    char* smc = (char*)smf;
    const u32 sb = smem_u32(smf);
    const int tid = threadIdx.x;
    const int lane = tid & 31;
    const int warp = tid >> 5;

    // ---- stage B = fp16(W3) in [j][n] layout ----
    for (int i = tid; i < 32768; i += NTHREADS) {
        int j = i >> 10, col = i & 1023;
        __half h = __float2half_rn(W3[i]);
        *(u16*)(smc + OFF_B + j * B_STRIDE + col * 2) = *(u16*)&h;
    }
    // ---- W2 fp16 [j][n], W1 padded fp16 [8][32] ----
    for (int i = tid; i < 1024; i += NTHREADS) {
        int j = i >> 5, n = i & 31;
        __half hh = __float2half_rn(W2[i]);
        *(u16*)(smc + OFF_W2H + j * W_STRIDE + n * 2) = *(u16*)&hh;
        smf[F_B3S + i] = b3[i];
    }
    for (int i = tid; i < 256; i += NTHREADS) {
        int j = i >> 5, n = i & 31;
        float w = (j < 5) ? W1[j * 32 + n] : 0.f;
        __half hh = __float2half_rn(w);
        *(u16*)(smc + OFF_W1H + j * W_STRIDE + n * 2) = *(u16*)&hh;
    }
    if (tid < 32) {
        smf[F_B1 + tid] = b1[tid];
        smf[F_B2 + tid] = b2[tid];
    }
    __syncthreads();

    const int g = lane >> 2;     // fragment row group
    const int tq = lane & 3;     // fragment col group
    float* xw = smf + (OFF_XS / 4) + warp * (32 * XS_STRIDE);
    int* dstw = (int*)(smc + OFF_DSTS) + warp * 32;
    const u32 efw = sb + OFF_EFS + (u32)(warp * 512);

    const int rowoff = ((lane >> 3) & 1) * 8 + (lane & 7);
    const int colb16 = (lane >> 4) * 16;
    // W1/W2 ldsm lane addressing
    const u32 w1addr = sb + OFF_W1H + (u32)((lane & 7) * W_STRIDE) +
                       (u32)((lane >> 3) * 16);
    const u32 efaddr0 = efw + (u32)((lane & 15) * 16);

    const int* srcp = eidx;
    const int* dstp = eidx + E;
    const int ntiles = (E + 31) >> 5;
    const int gw = blockIdx.x * NWARPS + warp;
    const int gstride = gridDim.x * NWARPS;

#define LOADB(FR, C)                                                        \
    do {                                                                    \
        u32 _bc = sb + OFF_B + (u32)((C) * 64 + colb16);                    \
        ldsm_x4t(FR[0], _bc + (u32)(rowoff * B_STRIDE));                    \
        ldsm_x4t(FR[1], _bc + (u32)((rowoff + 16) * B_STRIDE));             \
        ldsm_x4t(FR[2], _bc + 32 + (u32)(rowoff * B_STRIDE));               \
        ldsm_x4t(FR[3], _bc + 32 + (u32)((rowoff + 16) * B_STRIDE));        \
    } while (0)

#define CHUNK_BODY(BB, C, X00, X01, X10, X11)                               \
    do {                                                                    \
        const int _cb = (C) * 32;                                           \
        float acc[2][4][4];                                                 \
        _Pragma("unroll") for (int n8 = 0; n8 < 4; n8++) {                  \
            float2 bv =                                                     \
                *(const float2*)(smf + F_B3S + _cb + n8 * 8 + 2 * tq);      \
            _Pragma("unroll") for (int mt = 0; mt < 2; mt++) {              \
                acc[mt][n8][0] = bv.x;                                      \
                acc[mt][n8][1] = bv.y;                                      \
                acc[mt][n8][2] = bv.x;                                      \
                acc[mt][n8][3] = bv.y;                                      \
            }                                                               \
        }                                                                   \
        mma_f16(acc[0][0], Ah[0][0], BB[0][0], BB[0][1]);                   \
        mma_f16(acc[0][1], Ah[0][0], BB[0][2], BB[0][3]);                   \
        mma_f16(acc[1][0], Ah[1][0], BB[0][0], BB[0][1]);                   \
        mma_f16(acc[1][1], Ah[1][0], BB[0][2], BB[0][3]);                   \
        mma_f16(acc[0][2], Ah[0][0], BB[2][0], BB[2][1]);                   \
        mma_f16(acc[0][3], Ah[0][0], BB[2][2], BB[2][3]);                   \
        mma_f16(acc[1][2], Ah[1][0], BB[2][0], BB[2][1]);                   \
        mma_f16(acc[1][3], Ah[1][0], BB[2][2], BB[2][3]);                   \
        mma_f16(acc[0][0], Ah[0][1], BB[1][0], BB[1][1]);                   \
        mma_f16(acc[0][1], Ah[0][1], BB[1][2], BB[1][3]);                   \
        mma_f16(acc[1][0], Ah[1][1], BB[1][0], BB[1][1]);                   \
        mma_f16(acc[1][1], Ah[1][1], BB[1][2], BB[1][3]);                   \
        mma_f16(acc[0][2], Ah[0][1], BB[3][0], BB[3][1]);                   \
        mma_f16(acc[0][3], Ah[0][1], BB[3][2], BB[3][3]);                   \
        mma_f16(acc[1][2], Ah[1][1], BB[3][0], BB[3][1]);                   \
        mma_f16(acc[1][3], Ah[1][1], BB[3][2], BB[3][3]);                   \
        _Pragma("unroll") for (int t = 0; t < 4; t++) {                     \
            const float* d0 = acc[0][t];                                    \
            msg[0][0][2 * t] = fmaf(X00, fmaxf(d0[0], 0.f),                 \
                                    msg[0][0][2 * t]);                      \
            msg[0][0][2 * t + 1] = fmaf(X00, fmaxf(d0[1], 0.f),             \
                                        msg[0][0][2 * t + 1]);              \
            msg[0][1][2 * t] = fmaf(X01, fmaxf(d0[2], 0.f),                 \
                                    msg[0][1][2 * t]);                      \
            msg[0][1][2 * t + 1] = fmaf(X01, fmaxf(d0[3], 0.f),             \
                                        msg[0][1][2 * t + 1]);              \
            const float* d1 = acc[1][t];                                    \
            msg[1][0][2 * t] = fmaf(X10, fmaxf(d1[0], 0.f),                 \
                                    msg[1][0][2 * t]);                      \
            msg[1][0][2 * t + 1] = fmaf(X10, fmaxf(d1[1], 0.f),             \
                                        msg[1][0][2 * t + 1]);              \
            msg[1][1][2 * t] = fmaf(X11, fmaxf(d1[2], 0.f),                 \
                                    msg[1][1][2 * t]);                      \
            msg[1][1][2 * t + 1] = fmaf(X11, fmaxf(d1[3], 0.f),             \
                                        msg[1][1][2 * t + 1]);              \
        }                                                                   \
    } while (0)

    for (int tile = gw; tile < ntiles; tile += gstride) {
        // ---- per-tile weight fragments (independent of edge data) ----
        u32 w1f[4];                 // W1 B-frags: n8 tiles 0..3 (k=8)
        ldsm_x4t(w1f, w1addr);
        u32 w2f[2][2][4];           // [ni][kk]: n8 tiles 2ni,2ni+1
#pragma unroll
        for (int ni = 0; ni < 2; ni++) {
            u32 bch = sb + OFF_W2H + (u32)(ni * 32 + colb16);
            ldsm_x4t(w2f[ni][0], bch + (u32)(rowoff * W_STRIDE));
            ldsm_x4t(w2f[ni][1], bch + (u32)((rowoff + 16) * W_STRIDE));
        }

        // ================= phase 1: thread = edge =================
        int e = (tile << 5) + lane;
        bool valid = e < E;
        float vx = 0.f, vy = 0.f, vz = 0.f, ea = 0.f;
        int si = 0, di = -1;
        if (valid) {
            si = srcp[e];
            di = dstp[e];
            float px = positions[si * 3 + 0], py = positions[si * 3 + 1],
                  pz = positions[si * 3 + 2];
            float qx = positions[di * 3 + 0], qy = positions[di * 3 + 1],
                  qz = positions[di * 3 + 2];
            vx = qx - px + shifts[e * 3 + 0];
            vy = qy - py + shifts[e * 3 + 1];
            vz = qz - pz + shifts[e * 3 + 2];
            ea = edge_attr[e];
        }
        dstw[lane] = valid ? di : -1;
        float len = sqrtf(vx * vx + vy * vy + vz * vz);

        // ef row (8 fp16: vx,vy,vz,len,ea,0,0,0) -> one STS.128
        {
            u32 p0 = h2u(vx, vy);
            u32 p1 = h2u(vz, len);
            u32 p2 = h2u(ea, 0.f);
            u32 q[4] = {p0, p1, p2, 0u};
            *(uint4*)(smc + OFF_EFS + warp * 512 + lane * 16) =
                *(uint4*)q;
        }
        // x[src] -> xs
        if (valid) {
            const float4* xr = (const float4*)(g_x + (size_t)si * 32);
            float* xd = xw + lane * XS_STRIDE;
#pragma unroll
            for (int t = 0; t < 8; t++) *(float4*)(xd + 4 * t) = xr[t];
        }
        __syncwarp();

        // ================= h1 = relu(ef @ W1 + b1) in fragments ============
        float2 b1v[4];
#pragma unroll
        for (int j = 0; j < 4; j++)
            b1v[j] = *(const float2*)(smf + F_B1 + j * 8 + 2 * tq);

        u32 A1[2][2][4];   // h2 A-frags [mt][kk]
#pragma unroll
        for (int mt = 0; mt < 2; mt++) {
            u32 ef2[2];
            ldsm_x2(ef2, efaddr0 + (u32)(mt * 256));
            float a1[4][4];
#pragma unroll
            for (int j = 0; j < 4; j++) {
                a1[j][0] = b1v[j].x;
                a1[j][1] = b1v[j].y;
                a1[j][2] = b1v[j].x;
                a1[j][3] = b1v[j].y;
                mma_f16_k8(a1[j], ef2, w1f[j]);
            }
            // relu + cvt -> A-frags (D layout == A layout)
#pragma unroll
            for (int kk = 0; kk < 2; kk++) {
                const float* dA = a1[2 * kk];
                const float* dB = a1[2 * kk + 1];
                A1[mt][kk][0] = h2u(fmaxf(dA[0], 0.f), fmaxf(dA[1], 0.f));
                A1[mt][kk][1] = h2u(fmaxf(dA[2], 0.f), fmaxf(dA[3], 0.f));
                A1[mt][kk][2] = h2u(fmaxf(dB[0], 0.f), fmaxf(dB[1], 0.f));
                A1[mt][kk][3] = h2u(fmaxf(dB[2], 0.f), fmaxf(dB[3], 0.f));
            }
        }

        // ================= h2 = relu(h1 @ W2 + b2) in fragments ============
        float2 b2v[4];
#pragma unroll
        for (int j = 0; j < 4; j++)
            b2v[j] = *(const float2*)(smf + F_B2 + j * 8 + 2 * tq);

        u32 Ah[2][2][4];   // W3 A-frags [mt][kk]
#pragma unroll
        for (int mt = 0; mt < 2; mt++) {
            float a2[4][4];
#pragma unroll
            for (int n8 = 0; n8 < 4; n8++) {
                a2[n8][0] = b2v[n8].x;
                a2[n8][1] = b2v[n8].y;
                a2[n8][2] = b2v[n8].x;
                a2[n8][3] = b2v[n8].y;
            }
#pragma unroll
            for (int ni = 0; ni < 2; ni++)
#pragma unroll
                for (int kk = 0; kk < 2; kk++) {
                    mma_f16(a2[2 * ni + 0], A1[mt][kk], w2f[ni][kk][0],
                            w2f[ni][kk][1]);
                    mma_f16(a2[2 * ni + 1], A1[mt][kk], w2f[ni][kk][2],
                            w2f[ni][kk][3]);
                }
#pragma unroll
            for (int kk = 0; kk < 2; kk++) {
                const float* dA = a2[2 * kk];
                const float* dB = a2[2 * kk + 1];
                Ah[mt][kk][0] = h2u(fmaxf(dA[0], 0.f), fmaxf(dA[1], 0.f));
                Ah[mt][kk][1] = h2u(fmaxf(dA[2], 0.f), fmaxf(dA[3], 0.f));
                Ah[mt][kk][2] = h2u(fmaxf(dB[0], 0.f), fmaxf(dB[1], 0.f));
                Ah[mt][kk][3] = h2u(fmaxf(dB[2], 0.f), fmaxf(dB[3], 0.f));
            }
        }

        // ================= W3 chunk loop =================
        float msg[2][2][8];
#pragma unroll
        for (int a = 0; a < 2; a++)
#pragma unroll
            for (int hf = 0; hf < 2; hf++)
#pragma unroll
                for (int t = 0; t < 8; t++) msg[a][hf][t] = 0.f;

        u32 bbA[4][4], bbB[4][4];
        LOADB(bbA, 0);
#pragma unroll 1
        for (int c = 0; c < 32; c += 2) {
            LOADB(bbB, c + 1);
            float2 xp00 = *(const float2*)(xw + (g)*XS_STRIDE + c);
            float2 xp01 = *(const float2*)(xw + (8 + g) * XS_STRIDE + c);
            float2 xp10 = *(const float2*)(xw + (16 + g) * XS_STRIDE + c);
            float2 xp11 = *(const float2*)(xw + (24 + g) * XS_STRIDE + c);
            CHUNK_BODY(bbA, c, xp00.x, xp01.x, xp10.x, xp11.x);
            if (c + 2 < 32) LOADB(bbA, c + 2);
            CHUNK_BODY(bbB, c + 1, xp00.y, xp01.y, xp10.y, xp11.y);
        }

        // ================= scatter (vector atomics) =================
#pragma unroll
        for (int mt = 0; mt < 2; mt++)
#pragma unroll
            for (int hf = 0; hf < 2; hf++) {
                int row = mt * 16 + hf * 8 + g;
                int d = dstw[row];
                if (d >= 0) {
                    float* ap = g_agg + (size_t)d * 32 + 2 * tq;
#pragma unroll
                    for (int t = 0; t < 4; t++)
                        red_v2(ap + 8 * t, msg[mt][hf][2 * t],
                               msg[mt][hf][2 * t + 1]);
                }
            }
        __syncwarp();
    }
#undef LOADB
#undef CHUNK_BODY
}

// ---------------------------------------------------------------------------
__global__ void node_kernel(const float* __restrict__ conv_b, int N) {
    int idx = blockIdx.x * blockDim.x + threadIdx.x;
    if (idx < N * 32) {
        float v = g_agg[idx] + conv_b[idx & 31];
        g_x[idx] += fmaxf(v, 0.f);
        g_agg[idx] = 0.f;
    }
}

__global__ void pool_kernel(const int* __restrict__ batch_ids, int N) {
    int idx = blockIdx.x * blockDim.x + threadIdx.x;
    if (idx < N * 32) {
        int n = idx >> 5, k = idx & 31;
        int b = batch_ids[n];
        atomicAdd(&g_pooled[b * 32 + k], g_x[idx]);
        if (k == 0) atomicAdd(&g_counts[b], 1.f);
    }
}

__device__ __forceinline__ float selu_f(float x) {
    const float alpha = 1.6732632423543772f;
    const float scale = 1.0507009873554805f;
    return x > 0.f ? scale * x : scale * alpha * expm1f(x);
}

__global__ void mlp_kernel(const float* __restrict__ W1,
                           const float* __restrict__ b1,
                           const float* __restrict__ W2,
                           const float* __restrict__ b2,
                           const float* __restrict__ W3,
                           const float* __restrict__ b3,
                           const float* __restrict__ W4,
                           const float* __restrict__ b4,
                           float* __restrict__ out) {
    __shared__ float sbuf[32][280];
    int warp = threadIdx.x >> 5, lane = threadIdx.x & 31;
    int b = blockIdx.x * 32 + warp;
    if (b >= BATCH) return;
    float* buf = sbuf[warp];

    float cnt = fmaxf(g_counts[b], 1.f);
    buf[lane] = g_pooled[b * 32 + lane] / cnt;
    __syncwarp();

#pragma unroll
    for (int r = 0; r < 4; r++) {
        int o = lane + 32 * r;
        float a = b1[o];
        for (int k = 0; k < 32; k++) a = fmaf(buf[k], W1[k * 128 + o], a);
        buf[32 + o] = selu_f(a);
    }
    __syncwarp();
#pragma unroll
    for (int r = 0; r < 2; r++) {
        int o = lane + 32 * r;
        float a = b2[o];
        for (int k = 0; k < 128; k++) a = fmaf(buf[32 + k], W2[k * 64 + o], a);
        buf[160 + o] = selu_f(a);
    }
    __syncwarp();
    {
        int o = lane;
        float a = b3[o];
        for (int k = 0; k < 64; k++) a = fmaf(buf[160 + k], W3[k * 32 + o], a);
        buf[224 + o] = selu_f(a);
    }
    __syncwarp();
    if (lane < 21) {
        float a = b4[lane];
        for (int k = 0; k < 32; k++) a = fmaf(buf[224 + k], W4[k * 21 + lane], a);
        buf[256 + lane] = a;
    }
    __syncwarp();
    for (int r = lane; r < 36; r += 32) out[b * 36 + r] = buf[256 + c_IDX[r]];
}

// ---------------------------------------------------------------------------
extern "C" void kernel_launch(void* const* d_in, const int* in_sizes, int n_in,
                              void* d_out, int out_size) {
    const float* node_attrs = (const float*)d_in[0];
    const float* positions = (const float*)d_in[1];
    const float* shifts = (const float*)d_in[2];
    const float* edge_attr = (const float*)d_in[3];
    const int* edge_index = (const int*)d_in[4];
    const int* batch_ids = (const int*)d_in[5];
    const float* embed_W = (const float*)d_in[6];
    const float* embed_b = (const float*)d_in[7];
    const float* e_W1 = (const float*)d_in[8];
    const float* e_b1 = (const float*)d_in[9];
    const float* e_W2 = (const float*)d_in[10];
    const float* e_b2 = (const float*)d_in[11];
    const float* e_W3 = (const float*)d_in[12];
    const float* e_b3 = (const float*)d_in[13];
    const float* conv_b = (const float*)d_in[14];
    const float* h_W1 = (const float*)d_in[15];
    const float* h_b1 = (const float*)d_in[16];
    const float* h_W2 = (const float*)d_in[17];
    const float* h_b2 = (const float*)d_in[18];
    const float* h_W3 = (const float*)d_in[19];
    const float* h_b3 = (const float*)d_in[20];
    const float* h_W4 = (const float*)d_in[21];
    const float* h_b4 = (const float*)d_in[22];

    int N = in_sizes[0];
    int E = in_sizes[3];
    if (N > NMAX) N = NMAX;
    if (E > EMAX) E = EMAX;

    cudaFuncSetAttribute(edge_kernel,
                         cudaFuncAttributeMaxDynamicSharedMemorySize,
                         SMEM_TOTAL);

    int tot = N * 32;
    int blk = 256;
    init_kernel<<<(tot + blk - 1) / blk, blk>>>(node_attrs, embed_W, embed_b, N);

    for (int l = 0; l < 3; l++) {
        edge_kernel<<<148, NTHREADS, SMEM_TOTAL>>>(
            positions, shifts, edge_attr, edge_index, e_W1 + l * 160,
            e_b1 + l * 32, e_W2 + l * 1024, e_b2 + l * 32, e_W3 + l * 32768,
            e_b3 + l * 1024, E);
        node_kernel<<<(tot + blk - 1) / blk, blk>>>(conv_b + l * 32, N);
    }

    pool_kernel<<<(tot + blk - 1) / blk, blk>>>(batch_ids, N);
    mlp_kernel<<<2, 1024>>>(h_W1, h_b1, h_W2, h_b2, h_W3, h_b3, h_W4, h_b4,
                            (float*)d_out);
}

// round 14
// speedup vs baseline: 1.2170x; 1.0788x over previous
#include <cuda_runtime.h>
#include <cuda_fp16.h>
#include <math.h>

// ---------------------------------------------------------------------------
// NNConvNet fused GNN — R13: R12 fragment-MLP structure + 17 warps/CTA.
// 148*17 = 2516 warps over 10000 tiles -> max 4 tiles/warp (was 5 at 16
// warps): removes the ~18% wave-quantization tail. Pool fused into the
// last node_kernel. Chunk loop / scatter / staging unchanged (measured
// optimum).
// ---------------------------------------------------------------------------

#define NMAX 20000
#define EMAX 320000
#define BATCH 64
#define NWARPS 17
#define NTHREADS (NWARPS * 32)

typedef unsigned int u32;
typedef unsigned short u16;

__device__ float g_x[NMAX * 32];
__device__ float g_agg[NMAX * 32];
__device__ float g_pooled[BATCH * 32];
__device__ float g_counts[BATCH];

__constant__ int c_IDX[36] = {
    0, 1, 2,  3,  4,  5,
    1, 6, 7,  8,  9,  10,
    2, 7, 11, 12, 13, 14,
    3, 8, 12, 15, 16, 17,
    4, 9, 13, 16, 18, 19,
    5, 10,14, 17, 19, 20};

// ---------------- smem layout ----------------
// floats:
#define F_B1 0        // 32
#define F_B2 32       // 32
#define F_B3S 64      // 1024 (ends float idx 1088 = 4352 B)
// bytes:
#define OFF_W1H 4352                  // 8 rows * 80 B = 640 (ends 4992)
#define OFF_W2H 4992                  // 32 rows * 80 B = 2560 (ends 7552)
#define OFF_DSTS 7552                 // 17*32*4 = 2176 (ends 9728)
#define OFF_XS 9728                   // 17*32*36*4 = 78336 (ends 88064)
#define OFF_EFS 88064                 // 17*512 = 8704 (ends 96768)
#define OFF_B 96768                   // 32*2064 = 66048 (ends 162816)
#define B_STRIDE 2064
#define W_STRIDE 80
#define XS_STRIDE 36
#define SMEM_TOTAL 162816

// ---------------- PTX helpers ----------------
__device__ __forceinline__ u32 smem_u32(const void* p) {
    u32 a;
    asm("{ .reg .u64 t; cvta.to.shared.u64 t, %1; cvt.u32.u64 %0, t; }"
        : "=r"(a) : "l"(p));
    return a;
}
__device__ __forceinline__ void ldsm_x2(u32* r, u32 addr) {
    asm volatile(
        "ldmatrix.sync.aligned.m8n8.x2.shared.b16 {%0,%1}, [%2];"
        : "=r"(r[0]), "=r"(r[1]) : "r"(addr));
}
__device__ __forceinline__ void ldsm_x4t(u32* r, u32 addr) {
    asm volatile(
        "ldmatrix.sync.aligned.m8n8.x4.trans.shared.b16 {%0,%1,%2,%3}, [%4];"
        : "=r"(r[0]), "=r"(r[1]), "=r"(r[2]), "=r"(r[3]) : "r"(addr));
}
__device__ __forceinline__ void mma_f16(float* d, const u32* a, u32 b0,
                                        u32 b1) {
    asm volatile(
        "mma.sync.aligned.m16n8k16.row.col.f32.f16.f16.f32 "
        "{%0,%1,%2,%3}, {%4,%5,%6,%7}, {%8,%9}, {%0,%1,%2,%3};"
        : "+f"(d[0]), "+f"(d[1]), "+f"(d[2]), "+f"(d[3])
        : "r"(a[0]), "r"(a[1]), "r"(a[2]), "r"(a[3]), "r"(b0), "r"(b1));
}
__device__ __forceinline__ void mma_f16_k8(float* d, const u32* a, u32 b0) {
    asm volatile(
        "mma.sync.aligned.m16n8k8.row.col.f32.f16.f16.f32 "
        "{%0,%1,%2,%3}, {%4,%5}, {%6}, {%0,%1,%2,%3};"
        : "+f"(d[0]), "+f"(d[1]), "+f"(d[2]), "+f"(d[3])
        : "r"(a[0]), "r"(a[1]), "r"(b0));
}
__device__ __forceinline__ void red_v2(float* ap, float m0, float m1) {
    asm volatile("red.global.add.v2.f32 [%0], {%1, %2};"
                 :: "l"(ap), "f"(m0), "f"(m1) : "memory");
}
__device__ __forceinline__ u32 h2u(float lo, float hi) {
    __half2 h = __floats2half2_rn(lo, hi);
    return *(u32*)&h;
}

// ---------------------------------------------------------------------------
__global__ void init_kernel(const float* __restrict__ node_attrs,
                            const float* __restrict__ embW,
                            const float* __restrict__ embB, int N) {
    int idx = blockIdx.x * blockDim.x + threadIdx.x;
    if (idx < N * 32) {
        int k = idx & 31;
        g_x[idx] = fmaf(node_attrs[idx >> 5], embW[k], embB[k]);
        g_agg[idx] = 0.f;
    }
    if (idx < BATCH * 32) g_pooled[idx] = 0.f;
    if (idx < BATCH) g_counts[idx] = 0.f;
}

// ---------------------------------------------------------------------------
__global__ void __launch_bounds__(NTHREADS, 1)
edge_kernel(const float* __restrict__ positions,
            const float* __restrict__ shifts,
            const float* __restrict__ edge_attr,
            const int* __restrict__ eidx,
            const float* __restrict__ W1, const float* __restrict__ b1,
            const float* __restrict__ W2, const float* __restrict__ b2,
            const float* __restrict__ W3, const float* __restrict__ b3,
            int E) {
    extern __shared__ float smf[];
    char* smc = (char*)smf;
    const u32 sb = smem_u32(smf);
    const int tid = threadIdx.x;
    const int lane = tid & 31;
    const int warp = tid >> 5;

    // ---- stage B = fp16(W3) in [j][n] layout ----
    for (int i = tid; i < 32768; i += NTHREADS) {
        int j = i >> 10, col = i & 1023;
        __half h = __float2half_rn(W3[i]);
        *(u16*)(smc + OFF_B + j * B_STRIDE + col * 2) = *(u16*)&h;
    }
    // ---- W2 fp16 [j][n], W1 padded fp16 [8][32] ----
    for (int i = tid; i < 1024; i += NTHREADS) {
        int j = i >> 5, n = i & 31;
        __half hh = __float2half_rn(W2[i]);
        *(u16*)(smc + OFF_W2H + j * W_STRIDE + n * 2) = *(u16*)&hh;
        smf[F_B3S + i] = b3[i];
    }
    for (int i = tid; i < 256; i += NTHREADS) {
        int j = i >> 5, n = i & 31;
        float w = (j < 5) ? W1[j * 32 + n] : 0.f;
        __half hh = __float2half_rn(w);
        *(u16*)(smc + OFF_W1H + j * W_STRIDE + n * 2) = *(u16*)&hh;
    }
    if (tid < 32) {
        smf[F_B1 + tid] = b1[tid];
        smf[F_B2 + tid] = b2[tid];
    }
    __syncthreads();

    const int g = lane >> 2;     // fragment row group
    const int tq = lane & 3;     // fragment col group
    float* xw = smf + (OFF_XS / 4) + warp * (32 * XS_STRIDE);
    int* dstw = (int*)(smc + OFF_DSTS) + warp * 32;
    const u32 efw = sb + OFF_EFS + (u32)(warp * 512);

    const int rowoff = ((lane >> 3) & 1) * 8 + (lane & 7);
    const int colb16 = (lane >> 4) * 16;
    const u32 w1addr = sb + OFF_W1H + (u32)((lane & 7) * W_STRIDE) +
                       (u32)((lane >> 3) * 16);
    const u32 efaddr0 = efw + (u32)((lane & 15) * 16);

    const int* srcp = eidx;
    const int* dstp = eidx + E;
    const int ntiles = (E + 31) >> 5;
    const int gw = blockIdx.x * NWARPS + warp;
    const int gstride = gridDim.x * NWARPS;

#define LOADB(FR, C)                                                        \
    do {                                                                    \
        u32 _bc = sb + OFF_B + (u32)((C) * 64 + colb16);                    \
        ldsm_x4t(FR[0], _bc + (u32)(rowoff * B_STRIDE));                    \
        ldsm_x4t(FR[1], _bc + (u32)((rowoff + 16) * B_STRIDE));             \
        ldsm_x4t(FR[2], _bc + 32 + (u32)(rowoff * B_STRIDE));               \
        ldsm_x4t(FR[3], _bc + 32 + (u32)((rowoff + 16) * B_STRIDE));        \
    } while (0)

#define CHUNK_BODY(BB, C, X00, X01, X10, X11)                               \
    do {                                                                    \
        const int _cb = (C) * 32;                                           \
        float acc[2][4][4];                                                 \
        _Pragma("unroll") for (int n8 = 0; n8 < 4; n8++) {                  \
            float2 bv =                                                     \
                *(const float2*)(smf + F_B3S + _cb + n8 * 8 + 2 * tq);      \
            _Pragma("unroll") for (int mt = 0; mt < 2; mt++) {              \
                acc[mt][n8][0] = bv.x;                                      \
                acc[mt][n8][1] = bv.y;                                      \
                acc[mt][n8][2] = bv.x;                                      \
                acc[mt][n8][3] = bv.y;                                      \
            }                                                               \
        }                                                                   \
        mma_f16(acc[0][0], Ah[0][0], BB[0][0], BB[0][1]);                   \
        mma_f16(acc[0][1], Ah[0][0], BB[0][2], BB[0][3]);                   \
        mma_f16(acc[1][0], Ah[1][0], BB[0][0], BB[0][1]);                   \
        mma_f16(acc[1][1], Ah[1][0], BB[0][2], BB[0][3]);                   \
        mma_f16(acc[0][2], Ah[0][0], BB[2][0], BB[2][1]);                   \
        mma_f16(acc[0][3], Ah[0][0], BB[2][2], BB[2][3]);                   \
        mma_f16(acc[1][2], Ah[1][0], BB[2][0], BB[2][1]);                   \
        mma_f16(acc[1][3], Ah[1][0], BB[2][2], BB[2][3]);                   \
        mma_f16(acc[0][0], Ah[0][1], BB[1][0], BB[1][1]);                   \
        mma_f16(acc[0][1], Ah[0][1], BB[1][2], BB[1][3]);                   \
        mma_f16(acc[1][0], Ah[1][1], BB[1][0], BB[1][1]);                   \
        mma_f16(acc[1][1], Ah[1][1], BB[1][2], BB[1][3]);                   \
        mma_f16(acc[0][2], Ah[0][1], BB[3][0], BB[3][1]);                   \
        mma_f16(acc[0][3], Ah[0][1], BB[3][2], BB[3][3]);                   \
        mma_f16(acc[1][2], Ah[1][1], BB[3][0], BB[3][1]);                   \
        mma_f16(acc[1][3], Ah[1][1], BB[3][2], BB[3][3]);                   \
        _Pragma("unroll") for (int t = 0; t < 4; t++) {                     \
            const float* d0 = acc[0][t];                                    \
            msg[0][0][2 * t] = fmaf(X00, fmaxf(d0[0], 0.f),                 \
                                    msg[0][0][2 * t]);                      \
            msg[0][0][2 * t + 1] = fmaf(X00, fmaxf(d0[1], 0.f),             \
                                        msg[0][0][2 * t + 1]);              \
            msg[0][1][2 * t] = fmaf(X01, fmaxf(d0[2], 0.f),                 \
                                    msg[0][1][2 * t]);                      \
            msg[0][1][2 * t + 1] = fmaf(X01, fmaxf(d0[3], 0.f),             \
                                        msg[0][1][2 * t + 1]);              \
            const float* d1 = acc[1][t];                                    \
            msg[1][0][2 * t] = fmaf(X10, fmaxf(d1[0], 0.f),                 \
                                    msg[1][0][2 * t]);                      \
            msg[1][0][2 * t + 1] = fmaf(X10, fmaxf(d1[1], 0.f),             \
                                        msg[1][0][2 * t + 1]);              \
            msg[1][1][2 * t] = fmaf(X11, fmaxf(d1[2], 0.f),                 \
                                    msg[1][1][2 * t]);                      \
            msg[1][1][2 * t + 1] = fmaf(X11, fmaxf(d1[3], 0.f),             \
                                        msg[1][1][2 * t + 1]);              \
        }                                                                   \
    } while (0)

    for (int tile = gw; tile < ntiles; tile += gstride) {
        // ---- per-tile weight fragments ----
        u32 w1f[4];
        ldsm_x4t(w1f, w1addr);
        u32 w2f[2][2][4];
#pragma unroll
        for (int ni = 0; ni < 2; ni++) {
            u32 bch = sb + OFF_W2H + (u32)(ni * 32 + colb16);
            ldsm_x4t(w2f[ni][0], bch + (u32)(rowoff * W_STRIDE));
            ldsm_x4t(w2f[ni][1], bch + (u32)((rowoff + 16) * W_STRIDE));
        }

        // ================= phase 1: thread = edge =================
        int e = (tile << 5) + lane;
        bool valid = e < E;
        float vx = 0.f, vy = 0.f, vz = 0.f, ea = 0.f;
        int si = 0, di = -1;
        if (valid) {
            si = srcp[e];
            di = dstp[e];
            float px = positions[si * 3 + 0], py = positions[si * 3 + 1],
                  pz = positions[si * 3 + 2];
            float qx = positions[di * 3 + 0], qy = positions[di * 3 + 1],
                  qz = positions[di * 3 + 2];
            vx = qx - px + shifts[e * 3 + 0];
            vy = qy - py + shifts[e * 3 + 1];
            vz = qz - pz + shifts[e * 3 + 2];
            ea = edge_attr[e];
        }
        dstw[lane] = valid ? di : -1;
        float len = sqrtf(vx * vx + vy * vy + vz * vz);

        // ef row (8 fp16) -> one STS.128
        {
            u32 q[4] = {h2u(vx, vy), h2u(vz, len), h2u(ea, 0.f), 0u};
            *(uint4*)(smc + OFF_EFS + warp * 512 + lane * 16) = *(uint4*)q;
        }
        // x[src] -> xs
        if (valid) {
            const float4* xr = (const float4*)(g_x + (size_t)si * 32);
            float* xd = xw + lane * XS_STRIDE;
#pragma unroll
            for (int t = 0; t < 8; t++) *(float4*)(xd + 4 * t) = xr[t];
        }
        __syncwarp();

        // ================= h1 = relu(ef @ W1 + b1) in fragments ============
        float2 b1v[4];
#pragma unroll
        for (int j = 0; j < 4; j++)
            b1v[j] = *(const float2*)(smf + F_B1 + j * 8 + 2 * tq);

        u32 A1[2][2][4];
#pragma unroll
        for (int mt = 0; mt < 2; mt++) {
            u32 ef2[2];
            ldsm_x2(ef2, efaddr0 + (u32)(mt * 256));
            float a1[4][4];
#pragma unroll
            for (int j = 0; j < 4; j++) {
                a1[j][0] = b1v[j].x;
                a1[j][1] = b1v[j].y;
                a1[j][2] = b1v[j].x;
                a1[j][3] = b1v[j].y;
                mma_f16_k8(a1[j], ef2, w1f[j]);
            }
#pragma unroll
            for (int kk = 0; kk < 2; kk++) {
                const float* dA = a1[2 * kk];
                const float* dB = a1[2 * kk + 1];
                A1[mt][kk][0] = h2u(fmaxf(dA[0], 0.f), fmaxf(dA[1], 0.f));
                A1[mt][kk][1] = h2u(fmaxf(dA[2], 0.f), fmaxf(dA[3], 0.f));
                A1[mt][kk][2] = h2u(fmaxf(dB[0], 0.f), fmaxf(dB[1], 0.f));
                A1[mt][kk][3] = h2u(fmaxf(dB[2], 0.f), fmaxf(dB[3], 0.f));
            }
        }

        // ================= h2 = relu(h1 @ W2 + b2) in fragments ============
        float2 b2v[4];
#pragma unroll
        for (int j = 0; j < 4; j++)
            b2v[j] = *(const float2*)(smf + F_B2 + j * 8 + 2 * tq);

        u32 Ah[2][2][4];
#pragma unroll
        for (int mt = 0; mt < 2; mt++) {
            float a2[4][4];
#pragma unroll
            for (int n8 = 0; n8 < 4; n8++) {
                a2[n8][0] = b2v[n8].x;
                a2[n8][1] = b2v[n8].y;
                a2[n8][2] = b2v[n8].x;
                a2[n8][3] = b2v[n8].y;
            }
#pragma unroll
            for (int ni = 0; ni < 2; ni++)
#pragma unroll
                for (int kk = 0; kk < 2; kk++) {
                    mma_f16(a2[2 * ni + 0], A1[mt][kk], w2f[ni][kk][0],
                            w2f[ni][kk][1]);
                    mma_f16(a2[2 * ni + 1], A1[mt][kk], w2f[ni][kk][2],
                            w2f[ni][kk][3]);
                }
#pragma unroll
            for (int kk = 0; kk < 2; kk++) {
                const float* dA = a2[2 * kk];
                const float* dB = a2[2 * kk + 1];
                Ah[mt][kk][0] = h2u(fmaxf(dA[0], 0.f), fmaxf(dA[1], 0.f));
                Ah[mt][kk][1] = h2u(fmaxf(dA[2], 0.f), fmaxf(dA[3], 0.f));
                Ah[mt][kk][2] = h2u(fmaxf(dB[0], 0.f), fmaxf(dB[1], 0.f));
                Ah[mt][kk][3] = h2u(fmaxf(dB[2], 0.f), fmaxf(dB[3], 0.f));
            }
        }

        // ================= W3 chunk loop =================
        float msg[2][2][8];
#pragma unroll
        for (int a = 0; a < 2; a++)
#pragma unroll
            for (int hf = 0; hf < 2; hf++)
#pragma unroll
                for (int t = 0; t < 8; t++) msg[a][hf][t] = 0.f;

        u32 bbA[4][4], bbB[4][4];
        LOADB(bbA, 0);
#pragma unroll 1
        for (int c = 0; c < 32; c += 2) {
            LOADB(bbB, c + 1);
            float2 xp00 = *(const float2*)(xw + (g)*XS_STRIDE + c);
            float2 xp01 = *(const float2*)(xw + (8 + g) * XS_STRIDE + c);
            float2 xp10 = *(const float2*)(xw + (16 + g) * XS_STRIDE + c);
            float2 xp11 = *(const float2*)(xw + (24 + g) * XS_STRIDE + c);
            CHUNK_BODY(bbA, c, xp00.x, xp01.x, xp10.x, xp11.x);
            if (c + 2 < 32) LOADB(bbA, c + 2);
            CHUNK_BODY(bbB, c + 1, xp00.y, xp01.y, xp10.y, xp11.y);
        }

        // ================= scatter (vector atomics) =================
#pragma unroll
        for (int mt = 0; mt < 2; mt++)
#pragma unroll
            for (int hf = 0; hf < 2; hf++) {
                int row = mt * 16 + hf * 8 + g;
                int d = dstw[row];
                if (d >= 0) {
                    float* ap = g_agg + (size_t)d * 32 + 2 * tq;
#pragma unroll
                    for (int t = 0; t < 4; t++)
                        red_v2(ap + 8 * t, msg[mt][hf][2 * t],
                               msg[mt][hf][2 * t + 1]);
                }
            }
        __syncwarp();
    }
#undef LOADB
#undef CHUNK_BODY
}

// ---------------------------------------------------------------------------
// Node update; optionally fused pooling (last layer).
__global__ void node_kernel(const float* __restrict__ conv_b,
                            const int* __restrict__ batch_ids, int N,
                            int do_pool) {
    int idx = blockIdx.x * blockDim.x + threadIdx.x;
    if (idx < N * 32) {
        int k = idx & 31;
        float v = g_agg[idx] + conv_b[k];
        float nx = g_x[idx] + fmaxf(v, 0.f);
        g_x[idx] = nx;
        g_agg[idx] = 0.f;
        if (do_pool) {
            int n = idx >> 5;
            int b = batch_ids[n];
            atomicAdd(&g_pooled[b * 32 + k], nx);
            if (k == 0) atomicAdd(&g_counts[b], 1.f);
        }
    }
}

__device__ __forceinline__ float selu_f(float x) {
    const float alpha = 1.6732632423543772f;
    const float scale = 1.0507009873554805f;
    return x > 0.f ? scale * x : scale * alpha * expm1f(x);
}

__global__ void mlp_kernel(const float* __restrict__ W1,
                           const float* __restrict__ b1,
                           const float* __restrict__ W2,
                           const float* __restrict__ b2,
                           const float* __restrict__ W3,
                           const float* __restrict__ b3,
                           const float* __restrict__ W4,
                           const float* __restrict__ b4,
                           float* __restrict__ out) {
    __shared__ float sbuf[32][280];
    int warp = threadIdx.x >> 5, lane = threadIdx.x & 31;
    int b = blockIdx.x * 32 + warp;
    if (b >= BATCH) return;
    float* buf = sbuf[warp];

    float cnt = fmaxf(g_counts[b], 1.f);
    buf[lane] = g_pooled[b * 32 + lane] / cnt;
    __syncwarp();

#pragma unroll
    for (int r = 0; r < 4; r++) {
        int o = lane + 32 * r;
        float a = b1[o];
        for (int k = 0; k < 32; k++) a = fmaf(buf[k], W1[k * 128 + o], a);
        buf[32 + o] = selu_f(a);
    }
    __syncwarp();
#pragma unroll
    for (int r = 0; r < 2; r++) {
        int o = lane + 32 * r;
        float a = b2[o];
        for (int k = 0; k < 128; k++) a = fmaf(buf[32 + k], W2[k * 64 + o], a);
        buf[160 + o] = selu_f(a);
    }
    __syncwarp();
    {
        int o = lane;
        float a = b3[o];
        for (int k = 0; k < 64; k++) a = fmaf(buf[160 + k], W3[k * 32 + o], a);
        buf[224 + o] = selu_f(a);
    }
    __syncwarp();
    if (lane < 21) {
        float a = b4[lane];
        for (int k = 0; k < 32; k++) a = fmaf(buf[224 + k], W4[k * 21 + lane], a);
        buf[256 + lane] = a;
    }
    __syncwarp();
    for (int r = lane; r < 36; r += 32) out[b * 36 + r] = buf[256 + c_IDX[r]];
}

// ---------------------------------------------------------------------------
extern "C" void kernel_launch(void* const* d_in, const int* in_sizes, int n_in,
                              void* d_out, int out_size) {
    const float* node_attrs = (const float*)d_in[0];
    const float* positions = (const float*)d_in[1];
    const float* shifts = (const float*)d_in[2];
    const float* edge_attr = (const float*)d_in[3];
    const int* edge_index = (const int*)d_in[4];
    const int* batch_ids = (const int*)d_in[5];
    const float* embed_W = (const float*)d_in[6];
    const float* embed_b = (const float*)d_in[7];
    const float* e_W1 = (const float*)d_in[8];
    const float* e_b1 = (const float*)d_in[9];
    const float* e_W2 = (const float*)d_in[10];
    const float* e_b2 = (const float*)d_in[11];
    const float* e_W3 = (const float*)d_in[12];
    const float* e_b3 = (const float*)d_in[13];
    const float* conv_b = (const float*)d_in[14];
    const float* h_W1 = (const float*)d_in[15];
    const float* h_b1 = (const float*)d_in[16];
    const float* h_W2 = (const float*)d_in[17];
    const float* h_b2 = (const float*)d_in[18];
    const float* h_W3 = (const float*)d_in[19];
    const float* h_b3 = (const float*)d_in[20];
    const float* h_W4 = (const float*)d_in[21];
    const float* h_b4 = (const float*)d_in[22];

    int N = in_sizes[0];
    int E = in_sizes[3];
    if (N > NMAX) N = NMAX;
    if (E > EMAX) E = EMAX;

    cudaFuncSetAttribute(edge_kernel,
                         cudaFuncAttributeMaxDynamicSharedMemorySize,
                         SMEM_TOTAL);

    int tot = N * 32;
    int blk = 256;
    init_kernel<<<(tot + blk - 1) / blk, blk>>>(node_attrs, embed_W, embed_b, N);

    for (int l = 0; l < 3; l++) {
        edge_kernel<<<148, NTHREADS, SMEM_TOTAL>>>(
            positions, shifts, edge_attr, edge_index, e_W1 + l * 160,
            e_b1 + l * 32, e_W2 + l * 1024, e_b2 + l * 32, e_W3 + l * 32768,
            e_b3 + l * 1024, E);
        node_kernel<<<(tot + blk - 1) / blk, blk>>>(conv_b + l * 32, batch_ids,
                                                    N, l == 2 ? 1 : 0);
    }

    mlp_kernel<<<2, 1024>>>(h_W1, h_b1, h_W2, h_b2, h_W3, h_b3, h_W4, h_b4,
                            (float*)d_out);
}